// round 13
// baseline (speedup 1.0000x reference)
#include <cuda_runtime.h>
#include <cuda_fp16.h>
#include <cstdint>

#define NPTS 500000
#define NVOX 65536

// fp16 activation buffers
static __device__ __align__(16) __half g_pf1h [(size_t)NPTS * 64];
static __device__ __align__(16) __half g_pf2h [(size_t)NPTS * 128];
static __device__ __align__(16) __half g_pf4h [(size_t)NPTS * 256];
static __device__ __align__(16) __half g_pf5h [(size_t)NPTS * 256];
static __device__ __align__(16) __half g_vox1h[(size_t)NVOX * 128];
static __device__ __align__(16) __half g_vgh  [(size_t)NVOX * 128];
static __device__ __align__(16) __half g_vox2h[(size_t)NVOX * 256];
// Pre-transposed fp16 weights: [Wv1t 128x128][W3t 256x256][W4t][Wv2t][W2t 128x64]
static __device__ __align__(16) __half g_wth[221184];
// CSR structures for segment-max
static __device__ int g_cnt [NVOX];
static __device__ int g_offs[NVOX + 1];
static __device__ int g_cur [NVOX];
static __device__ int g_plist[NPTS];
static __device__ int g_bsum[64];

__device__ __forceinline__ uint32_t smem_u32(const void* p) {
    return (uint32_t)__cvta_generic_to_shared((void*)p);
}
__device__ __forceinline__ uint32_t packh2(float a, float b) {
    __half2 p = __floats2half2_rn(a, b);
    return *reinterpret_cast<uint32_t*>(&p);
}
__device__ __forceinline__ void ldmx4(uint32_t* r, uint32_t addr) {
    asm volatile("ldmatrix.sync.aligned.m8n8.x4.shared.b16 {%0,%1,%2,%3}, [%4];"
                 : "=r"(r[0]), "=r"(r[1]), "=r"(r[2]), "=r"(r[3]) : "r"(addr));
}
__device__ __forceinline__ void mma16816(float* d, const uint32_t* a, uint32_t b0, uint32_t b1) {
    asm volatile(
        "mma.sync.aligned.m16n8k16.row.col.f32.f16.f16.f32 "
        "{%0,%1,%2,%3}, {%4,%5,%6,%7}, {%8,%9}, {%0,%1,%2,%3};"
        : "+f"(d[0]), "+f"(d[1]), "+f"(d[2]), "+f"(d[3])
        : "r"(a[0]), "r"(a[1]), "r"(a[2]), "r"(a[3]), "r"(b0), "r"(b1));
}
__device__ __forceinline__ void cp16(uint32_t dst, const void* src, bool pred) {
    int sz = pred ? 16 : 0;
    asm volatile("cp.async.cg.shared.global [%0], [%1], 16, %2;"
                 :: "r"(dst), "l"(src), "r"(sz));
}
__device__ __forceinline__ void cp_commit() { asm volatile("cp.async.commit_group;"); }
__device__ __forceinline__ void cp_wait0()  { asm volatile("cp.async.wait_group 0;" ::: "memory"); }
__device__ __forceinline__ void cp_wait1()  { asm volatile("cp.async.wait_group 1;" ::: "memory"); }

// ---------------------------------------------------------------------------
// CSR build: zero counts -> histogram -> 3-phase scan -> scatter
// ---------------------------------------------------------------------------
__global__ void k_zcnt() {
    int i = blockIdx.x * 256 + threadIdx.x;
    if (i < NVOX) g_cnt[i] = 0;
}
__global__ void k_hist(const int* __restrict__ idx) {
    int i = blockIdx.x * 256 + threadIdx.x;
    if (i < NPTS) atomicAdd(&g_cnt[idx[i]], 1);
}
__global__ __launch_bounds__(1024) void k_scan1() {
    __shared__ int ss[1024];
    int t = threadIdx.x, b = blockIdx.x;
    int i = b * 1024 + t;
    int c = g_cnt[i];
    ss[t] = c;
    __syncthreads();
    for (int d = 1; d < 1024; d <<= 1) {
        int v = (t >= d) ? ss[t - d] : 0;
        __syncthreads();
        ss[t] += v;
        __syncthreads();
    }
    g_offs[i] = ss[t] - c;
    if (t == 1023) g_bsum[b] = ss[1023];
}
__global__ void k_scan2() {
    int t = threadIdx.x;                   // 64 threads
    __shared__ int sb[64];
    sb[t] = g_bsum[t];
    __syncthreads();
    if (t == 0) {
        int run = 0;
        for (int j = 0; j < 64; j++) { int c = sb[j]; sb[j] = run; run += c; }
        g_offs[NVOX] = run;
    }
    __syncthreads();
    g_bsum[t] = sb[t];
}
__global__ __launch_bounds__(1024) void k_scan3() {
    int t = threadIdx.x, b = blockIdx.x;
    int i = b * 1024 + t;
    int o = g_offs[i] + g_bsum[b];
    g_offs[i] = o;
    g_cur [i] = o;
}
__global__ void k_scatter(const int* __restrict__ idx) {
    int i = blockIdx.x * 256 + threadIdx.x;
    if (i < NPTS) {
        int v = idx[i];
        int pos = atomicAdd(&g_cur[v], 1);
        g_plist[pos] = i;
    }
}

// ---------------------------------------------------------------------------
// Per-voxel gather-max over CSR list (fp16, __hmax2). Empty voxel -> 0.
// ---------------------------------------------------------------------------
template <int NF>
__global__ __launch_bounds__(128) void k_vmax(const __half* __restrict__ src,
                                              __half* __restrict__ dst) {
    int t = threadIdx.x;
    int v, h2;
    if (NF == 256) { v = blockIdx.x;             h2 = t; }
    else           { v = blockIdx.x * 2 + (t >> 6); h2 = t & 63; }
    int s = g_offs[v], e = g_offs[v + 1];
    __half2 acc = __float2half2_rn(0.f);
    const __half2* sp = (const __half2*)src;
    for (int q = s; q < e; q++) {
        int p = g_plist[q];
        acc = __hmax2(acc, sp[(size_t)p * (NF / 2) + h2]);
    }
    ((__half2*)dst)[(size_t)v * (NF / 2) + h2] = acc;
}

// ---------------------------------------------------------------------------
// Weight prep: W[K,Nf] fp32 -> Wt[Nf,K] fp16 (transposed)
// ---------------------------------------------------------------------------
__global__ void k_prep(const float* __restrict__ Wv1, const float* __restrict__ W3,
                       const float* __restrict__ W4,  const float* __restrict__ Wv2,
                       const float* __restrict__ W2) {
    int i = blockIdx.x * 256 + threadIdx.x;
    if (i >= 221184) return;
    const float* W; int K, Nf, j = i;
    if (i < 16384)       { W = Wv1; K = 128; Nf = 128; }
    else if (i < 81920)  { W = W3;  K = 256; Nf = 256; j = i - 16384; }
    else if (i < 147456) { W = W4;  K = 256; Nf = 256; j = i - 81920; }
    else if (i < 212992) { W = Wv2; K = 256; Nf = 256; j = i - 147456; }
    else                 { W = W2;  K = 64;  Nf = 128; j = i - 212992; }
    int n = j / K, k = j - n * K;
    g_wth[i] = __float2half_rn(W[(size_t)k * Nf + n]);
}

// ---------------------------------------------------------------------------
// K1a: per-point MLP 6 -> 64, write pf1 fp16
// ---------------------------------------------------------------------------
__global__ __launch_bounds__(256) void k1a_pointwise(
    const float* __restrict__ inp,
    const float* __restrict__ W1, const float* __restrict__ b1)
{
    __shared__ __align__(16) float sW1[6 * 64];
    __shared__ __align__(16) float sb1[64];
    int t = threadIdx.x;
    for (int i = t; i < 6 * 64; i += 256) sW1[i] = W1[i];
    if (t < 64) sb1[t] = b1[t];
    __syncthreads();

    int i = blockIdx.x * 256 + t;
    if (i >= NPTS) return;

    float x[6];
#pragma unroll
    for (int c = 0; c < 6; c++) x[c] = inp[(size_t)i * 6 + c];

    uint32_t outv[32];
#pragma unroll
    for (int j2 = 0; j2 < 32; j2++) {
        float a0 = sb1[j2 * 2], a1 = sb1[j2 * 2 + 1];
#pragma unroll
        for (int c = 0; c < 6; c++) {
            a0 = fmaf(x[c], sW1[c * 64 + j2 * 2], a0);
            a1 = fmaf(x[c], sW1[c * 64 + j2 * 2 + 1], a1);
        }
        outv[j2] = packh2(fmaxf(a0, 0.f), fmaxf(a1, 0.f));
    }
    uint4* dst = (uint4*)(g_pf1h + (size_t)i * 64);
#pragma unroll
    for (int q = 0; q < 8; q++) dst[q] = ((uint4*)outv)[q];
}

// ---------------------------------------------------------------------------
// HMMA GEMM, fp16: C[p,f] = relu( A[p,:] . Wt[f,:] + bias[f] )
// Block 128x128, K-chunk 32, 8 warps (32x64 warp tile, 4x2 grid), 3-stage
// cp.async, 256 threads, 2 CTAs/SM (launch_bounds-capped regs).
//   MODEB 0: A rows from ah[p*K + k]
//   MODEB 1: k<128 from gh[idx[p]*128+k], else ah[p*128 + (k-128)]
//   CVTOUT 1: fp16 store Ch;  CVTOUT 0: fp32 store C
// Stage layout: A[128x80B] @0, B @10240  (stage = 20480B)
// ---------------------------------------------------------------------------
template <int KCHUNKS, int MODEB, int CVTOUT>
__global__ __launch_bounds__(256, 2) void k_hmma(
    const __half* __restrict__ ah, const __half* __restrict__ gh,
    const int* __restrict__ idx,
    const __half* __restrict__ wth,
    const float* __restrict__ bias,
    float* __restrict__ C, __half* __restrict__ Ch,
    int M, int Nf)
{
    constexpr int K = KCHUNKS * 32;
    constexpr int STG = 20480;
    constexpr int AOFF = 0, BOFF = 10240;
    constexpr int IDX_OFF = 3 * STG;

    extern __shared__ char sm[];
    int* sIdx = (int*)(sm + IDX_OFF);
    uint32_t smb = smem_u32(sm);

    int t = threadIdx.x;
    int lane = t & 31;
    int w = t >> 5;
    int wm = w & 3, wn = w >> 2;     // 4 M-groups of 32, 2 N-groups of 64
    int p0 = blockIdx.x * 128;
    int f0 = blockIdx.y * 128;

    if (MODEB == 1) {
        if (t < 128) sIdx[t] = (p0 + t < M) ? idx[p0 + t] : 0;
        __syncthreads();
    }

    auto fill = [&](int s, int c) {
        int k0 = c * 32;
        uint32_t base = smb + s * STG;
        // A tile: 512 x 16B over 256 threads
#pragma unroll
        for (int it = 0; it < 2; it++) {
            int e = t + it * 256;
            int row = e >> 2, q = e & 3;
            int gp = p0 + row;
            const __half* srcp;
            if (MODEB == 0) {
                srcp = ah + (size_t)gp * K + k0 + q * 8;
            } else {
                if (k0 < 128) srcp = gh + (size_t)sIdx[row] * 128 + k0 + q * 8;
                else          srcp = ah + (size_t)gp * 128 + (k0 - 128) + q * 8;
            }
            cp16(base + AOFF + row * 80 + q * 16, srcp, gp < M);
        }
        // B tile: 512 x 16B
#pragma unroll
        for (int it = 0; it < 2; it++) {
            int e = t + it * 256;
            int n = e >> 2, q = e & 3;
            const __half* srcp = wth + (size_t)(f0 + n) * K + k0 + q * 8;
            cp16(base + BOFF + n * 80 + q * 16, srcp, true);
        }
        cp_commit();
    };

    float acc[2][8][4];
#pragma unroll
    for (int i = 0; i < 2; i++)
#pragma unroll
        for (int j = 0; j < 8; j++)
#pragma unroll
            for (int r = 0; r < 4; r++) acc[i][j][r] = 0.f;

    int ar  = ((lane >> 3) & 1) * 8 + (lane & 7);
    int akb = (lane >> 4) * 16;
    int bn  = (lane >> 4) * 8 + (lane & 7);
    int bkb = ((lane >> 3) & 1) * 16;

    fill(0, 0);
    if (KCHUNKS > 1) fill(1, 1);

#pragma unroll 1
    for (int c = 0; c < KCHUNKS; c++) {
        if (c + 1 < KCHUNKS) cp_wait1(); else cp_wait0();
        __syncthreads();
        if (c + 2 < KCHUNKS) fill((c + 2) % 3, c + 2);
        uint32_t base = smb + (c % 3) * STG;
#pragma unroll
        for (int ks = 0; ks < 2; ks++) {
            int kb = ks * 32;
            uint32_t a[2][4], bh[4][4];
#pragma unroll
            for (int i = 0; i < 2; i++)
                ldmx4(a[i], base + AOFF + (uint32_t)(wm * 32 + i * 16 + ar) * 80 + kb + akb);
#pragma unroll
            for (int j2 = 0; j2 < 4; j2++)
                ldmx4(bh[j2], base + BOFF + (uint32_t)(wn * 64 + j2 * 16 + bn) * 80 + kb + bkb);
#pragma unroll
            for (int i = 0; i < 2; i++)
#pragma unroll
                for (int j = 0; j < 8; j++)
                    mma16816(acc[i][j], a[i], bh[j >> 1][(j & 1) * 2], bh[j >> 1][(j & 1) * 2 + 1]);
        }
        __syncthreads();
    }

    // ---- epilogue: bias + relu, store ----
#pragma unroll
    for (int i = 0; i < 2; i++) {
        int pa = p0 + wm * 32 + i * 16 + (lane >> 2);
        int pb = pa + 8;
#pragma unroll
        for (int j = 0; j < 8; j++) {
            int f = f0 + wn * 64 + j * 8 + (lane & 3) * 2;
            float2 bj = *(const float2*)(bias + f);
            float v0 = fmaxf(acc[i][j][0] + bj.x, 0.f);
            float v1 = fmaxf(acc[i][j][1] + bj.y, 0.f);
            float v2 = fmaxf(acc[i][j][2] + bj.x, 0.f);
            float v3 = fmaxf(acc[i][j][3] + bj.y, 0.f);
            if (CVTOUT) {
                if (pa < M) *(uint32_t*)(Ch + (size_t)pa * Nf + f) = packh2(v0, v1);
                if (pb < M) *(uint32_t*)(Ch + (size_t)pb * Nf + f) = packh2(v2, v3);
            } else {
                if (pa < M) *(float2*)(C + (size_t)pa * Nf + f) = make_float2(v0, v1);
                if (pb < M) *(float2*)(C + (size_t)pb * Nf + f) = make_float2(v2, v3);
            }
        }
    }
}

// ---------------------------------------------------------------------------
extern "C" void kernel_launch(void* const* d_in, const int* in_sizes, int n_in,
                              void* d_out, int out_size)
{
    const float* inp = (const float*)d_in[0];
    const int*   idx = (const int*)d_in[1];   // int32 (JAX x64 disabled)
    const float* W1  = (const float*)d_in[2];
    const float* b1  = (const float*)d_in[3];
    const float* W2  = (const float*)d_in[4];
    const float* b2  = (const float*)d_in[5];
    const float* Wv1 = (const float*)d_in[6];
    const float* bv1 = (const float*)d_in[7];
    const float* W3  = (const float*)d_in[8];
    const float* b3  = (const float*)d_in[9];
    const float* W4  = (const float*)d_in[10];
    const float* b4  = (const float*)d_in[11];
    const float* Wv2 = (const float*)d_in[12];
    const float* bv2 = (const float*)d_in[13];
    float* out = (float*)d_out;

    __half *pf1h, *pf2h, *pf4h, *pf5h, *vox1h, *vgh, *vox2h, *wth;
    cudaGetSymbolAddress((void**)&pf1h,  g_pf1h);
    cudaGetSymbolAddress((void**)&pf2h,  g_pf2h);
    cudaGetSymbolAddress((void**)&pf4h,  g_pf4h);
    cudaGetSymbolAddress((void**)&pf5h,  g_pf5h);
    cudaGetSymbolAddress((void**)&vox1h, g_vox1h);
    cudaGetSymbolAddress((void**)&vgh,   g_vgh);
    cudaGetSymbolAddress((void**)&vox2h, g_vox2h);
    cudaGetSymbolAddress((void**)&wth,   g_wth);

    const int SMEM = 3 * 20480 + 512;
    cudaFuncSetAttribute(k_hmma<2,0,1>, cudaFuncAttributeMaxDynamicSharedMemorySize, SMEM);
    cudaFuncSetAttribute(k_hmma<4,0,1>, cudaFuncAttributeMaxDynamicSharedMemorySize, SMEM);
    cudaFuncSetAttribute(k_hmma<8,1,1>, cudaFuncAttributeMaxDynamicSharedMemorySize, SMEM);
    cudaFuncSetAttribute(k_hmma<8,0,1>, cudaFuncAttributeMaxDynamicSharedMemorySize, SMEM);
    cudaFuncSetAttribute(k_hmma<8,0,0>, cudaFuncAttributeMaxDynamicSharedMemorySize, SMEM);

    // CSR build
    k_zcnt<<<(NVOX + 255) / 256, 256>>>();
    k_prep<<<(221184 + 255) / 256, 256>>>(Wv1, W3, W4, Wv2, W2);
    k_hist<<<(NPTS + 255) / 256, 256>>>(idx);
    k_scan1<<<64, 1024>>>();
    k_scan2<<<1, 64>>>();
    k_scan3<<<64, 1024>>>();
    k_scatter<<<(NPTS + 255) / 256, 256>>>(idx);

    // 1a) point MLP 6->64 -> pf1 fp16
    k1a_pointwise<<<(NPTS + 255) / 256, 256>>>(inp, W1, b1);
    // 1b) pf2 = relu(pf1 @ W2 + b2) -> fp16
    k_hmma<2,0,1><<<dim3((NPTS + 127) / 128, 1), 256, SMEM>>>(
        pf1h, nullptr, nullptr, wth + 212992, b2, nullptr, pf2h, NPTS, 128);
    // 1c) vox1 = segment-max(pf2) via CSR gather
    k_vmax<128><<<NVOX / 2, 128>>>(pf2h, vox1h);

    // 2) vg = relu(vox1 @ Wv1 + bv1) -> fp16
    k_hmma<4,0,1><<<dim3(NVOX / 128, 1), 256, SMEM>>>(
        vox1h, nullptr, nullptr, wth + 0, bv1, nullptr, vgh, NVOX, 128);
    // 3) pf4 = relu(concat(vg[idx], pf2) @ W3 + b3) -> fp16
    k_hmma<8,1,1><<<dim3((NPTS + 127) / 128, 2), 256, SMEM>>>(
        pf2h, vgh, idx, wth + 16384, b3, nullptr, pf4h, NPTS, 256);
    // 4) pf5 = relu(pf4 @ W4 + b4) -> fp16
    k_hmma<8,0,1><<<dim3((NPTS + 127) / 128, 2), 256, SMEM>>>(
        pf4h, nullptr, nullptr, wth + 81920, b4, nullptr, pf5h, NPTS, 256);
    // 4b) vox2 = segment-max(pf5) via CSR gather
    k_vmax<256><<<NVOX, 128>>>(pf5h, vox2h);

    // 5) out = relu(vox2 @ Wv2 + bv2) (fp32 store)
    k_hmma<8,0,0><<<dim3(NVOX / 128, 2), 256, SMEM>>>(
        vox2h, nullptr, nullptr, wth + 147456, bv2, out, nullptr, NVOX, 256);
}

// round 14
// speedup vs baseline: 1.0571x; 1.0571x over previous
#include <cuda_runtime.h>
#include <cuda_fp16.h>
#include <cstdint>

#define NPTS 500000
#define NVOX 65536

// fp16 activation buffers
static __device__ __align__(16) __half g_pf1h [(size_t)NPTS * 64];
static __device__ __align__(16) __half g_pf2h [(size_t)NPTS * 128];
static __device__ __align__(16) __half g_pf4h [(size_t)NPTS * 256];
static __device__ __align__(16) __half g_pf5h [(size_t)NPTS * 256];
static __device__ __align__(16) __half g_vox1h[(size_t)NVOX * 128];
static __device__ __align__(16) __half g_vgh  [(size_t)NVOX * 128];
static __device__ __align__(16) __half g_vox2h[(size_t)NVOX * 256];
// Pre-transposed fp16 weights: [Wv1t 128x128][W3t 256x256][W4t][Wv2t][W2t 128x64]
static __device__ __align__(16) __half g_wth[221184];
// CSR structures for segment-max
static __device__ int g_cnt [NVOX];
static __device__ int g_offs[NVOX + 1];
static __device__ int g_cur [NVOX];
static __device__ int g_plist[NPTS];
static __device__ int g_bsum[64];

__device__ __forceinline__ uint32_t smem_u32(const void* p) {
    return (uint32_t)__cvta_generic_to_shared((void*)p);
}
__device__ __forceinline__ uint32_t packh2(float a, float b) {
    __half2 p = __floats2half2_rn(a, b);
    return *reinterpret_cast<uint32_t*>(&p);
}
__device__ __forceinline__ void ldmx4(uint32_t* r, uint32_t addr) {
    asm volatile("ldmatrix.sync.aligned.m8n8.x4.shared.b16 {%0,%1,%2,%3}, [%4];"
                 : "=r"(r[0]), "=r"(r[1]), "=r"(r[2]), "=r"(r[3]) : "r"(addr));
}
__device__ __forceinline__ void mma16816(float* d, const uint32_t* a, uint32_t b0, uint32_t b1) {
    asm volatile(
        "mma.sync.aligned.m16n8k16.row.col.f32.f16.f16.f32 "
        "{%0,%1,%2,%3}, {%4,%5,%6,%7}, {%8,%9}, {%0,%1,%2,%3};"
        : "+f"(d[0]), "+f"(d[1]), "+f"(d[2]), "+f"(d[3])
        : "r"(a[0]), "r"(a[1]), "r"(a[2]), "r"(a[3]), "r"(b0), "r"(b1));
}
__device__ __forceinline__ void cp16(uint32_t dst, const void* src, bool pred) {
    int sz = pred ? 16 : 0;
    asm volatile("cp.async.cg.shared.global [%0], [%1], 16, %2;"
                 :: "r"(dst), "l"(src), "r"(sz));
}
__device__ __forceinline__ void cp_commit() { asm volatile("cp.async.commit_group;"); }
__device__ __forceinline__ void cp_wait0()  { asm volatile("cp.async.wait_group 0;" ::: "memory"); }
__device__ __forceinline__ void cp_wait1()  { asm volatile("cp.async.wait_group 1;" ::: "memory"); }

// ---------------------------------------------------------------------------
// CSR build: zero counts -> histogram -> 3-phase scan -> scatter
// ---------------------------------------------------------------------------
__global__ void k_zcnt() {
    int i = blockIdx.x * 256 + threadIdx.x;
    if (i < NVOX) g_cnt[i] = 0;
}
__global__ void k_hist(const int* __restrict__ idx) {
    int i = blockIdx.x * 256 + threadIdx.x;
    if (i < NPTS) atomicAdd(&g_cnt[idx[i]], 1);
}
__global__ __launch_bounds__(1024) void k_scan1() {
    __shared__ int ss[1024];
    int t = threadIdx.x, b = blockIdx.x;
    int i = b * 1024 + t;
    int c = g_cnt[i];
    ss[t] = c;
    __syncthreads();
    for (int d = 1; d < 1024; d <<= 1) {
        int v = (t >= d) ? ss[t - d] : 0;
        __syncthreads();
        ss[t] += v;
        __syncthreads();
    }
    g_offs[i] = ss[t] - c;
    if (t == 1023) g_bsum[b] = ss[1023];
}
__global__ void k_scan2() {
    int t = threadIdx.x;                   // 64 threads
    __shared__ int sb[64];
    sb[t] = g_bsum[t];
    __syncthreads();
    if (t == 0) {
        int run = 0;
        for (int j = 0; j < 64; j++) { int c = sb[j]; sb[j] = run; run += c; }
        g_offs[NVOX] = run;
    }
    __syncthreads();
    g_bsum[t] = sb[t];
}
__global__ __launch_bounds__(1024) void k_scan3() {
    int t = threadIdx.x, b = blockIdx.x;
    int i = b * 1024 + t;
    int o = g_offs[i] + g_bsum[b];
    g_offs[i] = o;
    g_cur [i] = o;
}
__global__ void k_scatter(const int* __restrict__ idx) {
    int i = blockIdx.x * 256 + threadIdx.x;
    if (i < NPTS) {
        int v = idx[i];
        int pos = atomicAdd(&g_cur[v], 1);
        g_plist[pos] = i;
    }
}

// ---------------------------------------------------------------------------
// Per-voxel gather-max over CSR list (fp16, __hmax2). Empty voxel -> 0.
// ---------------------------------------------------------------------------
template <int NF>
__global__ __launch_bounds__(128) void k_vmax(const __half* __restrict__ src,
                                              __half* __restrict__ dst) {
    int t = threadIdx.x;
    int v, h2;
    if (NF == 256) { v = blockIdx.x;             h2 = t; }
    else           { v = blockIdx.x * 2 + (t >> 6); h2 = t & 63; }
    int s = g_offs[v], e = g_offs[v + 1];
    __half2 acc = __float2half2_rn(0.f);
    const __half2* sp = (const __half2*)src;
    for (int q = s; q < e; q++) {
        int p = g_plist[q];
        acc = __hmax2(acc, sp[(size_t)p * (NF / 2) + h2]);
    }
    ((__half2*)dst)[(size_t)v * (NF / 2) + h2] = acc;
}

// ---------------------------------------------------------------------------
// Weight prep: W[K,Nf] fp32 -> Wt[Nf,K] fp16 (transposed)
// ---------------------------------------------------------------------------
__global__ void k_prep(const float* __restrict__ Wv1, const float* __restrict__ W3,
                       const float* __restrict__ W4,  const float* __restrict__ Wv2,
                       const float* __restrict__ W2) {
    int i = blockIdx.x * 256 + threadIdx.x;
    if (i >= 221184) return;
    const float* W; int K, Nf, j = i;
    if (i < 16384)       { W = Wv1; K = 128; Nf = 128; }
    else if (i < 81920)  { W = W3;  K = 256; Nf = 256; j = i - 16384; }
    else if (i < 147456) { W = W4;  K = 256; Nf = 256; j = i - 81920; }
    else if (i < 212992) { W = Wv2; K = 256; Nf = 256; j = i - 147456; }
    else                 { W = W2;  K = 64;  Nf = 128; j = i - 212992; }
    int n = j / K, k = j - n * K;
    g_wth[i] = __float2half_rn(W[(size_t)k * Nf + n]);
}

// ---------------------------------------------------------------------------
// K1a: per-point MLP 6 -> 64, write pf1 fp16
// ---------------------------------------------------------------------------
__global__ __launch_bounds__(256) void k1a_pointwise(
    const float* __restrict__ inp,
    const float* __restrict__ W1, const float* __restrict__ b1)
{
    __shared__ __align__(16) float sW1[6 * 64];
    __shared__ __align__(16) float sb1[64];
    int t = threadIdx.x;
    for (int i = t; i < 6 * 64; i += 256) sW1[i] = W1[i];
    if (t < 64) sb1[t] = b1[t];
    __syncthreads();

    int i = blockIdx.x * 256 + t;
    if (i >= NPTS) return;

    float x[6];
#pragma unroll
    for (int c = 0; c < 6; c++) x[c] = inp[(size_t)i * 6 + c];

    uint32_t outv[32];
#pragma unroll
    for (int j2 = 0; j2 < 32; j2++) {
        float a0 = sb1[j2 * 2], a1 = sb1[j2 * 2 + 1];
#pragma unroll
        for (int c = 0; c < 6; c++) {
            a0 = fmaf(x[c], sW1[c * 64 + j2 * 2], a0);
            a1 = fmaf(x[c], sW1[c * 64 + j2 * 2 + 1], a1);
        }
        outv[j2] = packh2(fmaxf(a0, 0.f), fmaxf(a1, 0.f));
    }
    uint4* dst = (uint4*)(g_pf1h + (size_t)i * 64);
#pragma unroll
    for (int q = 0; q < 8; q++) dst[q] = ((uint4*)outv)[q];
}

// ---------------------------------------------------------------------------
// HMMA GEMM, fp16: C[p,f] = relu( A[p,:] . Wt[f,:] + bias[f] )
// Block 128x128, K-chunk 32, 4 warps (64x64 warp tile), 3-stage cp.async,
// 128 threads, 3 CTAs/SM (launch_bounds-capped).
//   MODEB 0: A rows from ah[p*K + k]
//   MODEB 1: k<128 from gh[idx[p]*128+k], else ah[p*128 + (k-128)]
//   CVTOUT 1: fp16 store Ch;  CVTOUT 0: fp32 store C
// Stage layout: A[128x80B] @0, B @10240  (stage = 20480B)
// ---------------------------------------------------------------------------
template <int KCHUNKS, int MODEB, int CVTOUT>
__global__ __launch_bounds__(128, 3) void k_hmma(
    const __half* __restrict__ ah, const __half* __restrict__ gh,
    const int* __restrict__ idx,
    const __half* __restrict__ wth,
    const float* __restrict__ bias,
    float* __restrict__ C, __half* __restrict__ Ch,
    int M, int Nf)
{
    constexpr int K = KCHUNKS * 32;
    constexpr int STG = 20480;
    constexpr int AOFF = 0, BOFF = 10240;
    constexpr int IDX_OFF = 3 * STG;

    extern __shared__ char sm[];
    int* sIdx = (int*)(sm + IDX_OFF);
    uint32_t smb = smem_u32(sm);

    int t = threadIdx.x;
    int lane = t & 31;
    int w = t >> 5;
    int wm = w & 1, wn = w >> 1;
    int p0 = blockIdx.x * 128;
    int f0 = blockIdx.y * 128;

    if (MODEB == 1) {
        if (t < 128) sIdx[t] = (p0 + t < M) ? idx[p0 + t] : 0;
        __syncthreads();
    }

    auto fill = [&](int s, int c) {
        int k0 = c * 32;
        uint32_t base = smb + s * STG;
#pragma unroll
        for (int it = 0; it < 4; it++) {
            int e = t + it * 128;
            int row = e >> 2, q = e & 3;
            int gp = p0 + row;
            const __half* srcp;
            if (MODEB == 0) {
                srcp = ah + (size_t)gp * K + k0 + q * 8;
            } else {
                if (k0 < 128) srcp = gh + (size_t)sIdx[row] * 128 + k0 + q * 8;
                else          srcp = ah + (size_t)gp * 128 + (k0 - 128) + q * 8;
            }
            cp16(base + AOFF + row * 80 + q * 16, srcp, gp < M);
        }
#pragma unroll
        for (int it = 0; it < 4; it++) {
            int e = t + it * 128;
            int n = e >> 2, q = e & 3;
            const __half* srcp = wth + (size_t)(f0 + n) * K + k0 + q * 8;
            cp16(base + BOFF + n * 80 + q * 16, srcp, true);
        }
        cp_commit();
    };

    float acc[4][8][4];
#pragma unroll
    for (int i = 0; i < 4; i++)
#pragma unroll
        for (int j = 0; j < 8; j++)
#pragma unroll
            for (int r = 0; r < 4; r++) acc[i][j][r] = 0.f;

    int ar  = ((lane >> 3) & 1) * 8 + (lane & 7);
    int akb = (lane >> 4) * 16;
    int bn  = (lane >> 4) * 8 + (lane & 7);
    int bkb = ((lane >> 3) & 1) * 16;

    fill(0, 0);
    if (KCHUNKS > 1) fill(1, 1);

#pragma unroll 1
    for (int c = 0; c < KCHUNKS; c++) {
        if (c + 1 < KCHUNKS) cp_wait1(); else cp_wait0();
        __syncthreads();
        if (c + 2 < KCHUNKS) fill((c + 2) % 3, c + 2);
        uint32_t base = smb + (c % 3) * STG;
#pragma unroll
        for (int ks = 0; ks < 2; ks++) {
            int kb = ks * 32;
            uint32_t a[4][4], bh[4][4];
#pragma unroll
            for (int i = 0; i < 4; i++)
                ldmx4(a[i], base + AOFF + (uint32_t)(wm * 64 + i * 16 + ar) * 80 + kb + akb);
#pragma unroll
            for (int j2 = 0; j2 < 4; j2++)
                ldmx4(bh[j2], base + BOFF + (uint32_t)(wn * 64 + j2 * 16 + bn) * 80 + kb + bkb);
#pragma unroll
            for (int i = 0; i < 4; i++)
#pragma unroll
                for (int j = 0; j < 8; j++)
                    mma16816(acc[i][j], a[i], bh[j >> 1][(j & 1) * 2], bh[j >> 1][(j & 1) * 2 + 1]);
        }
        __syncthreads();
    }

    // ---- epilogue: bias + relu, store ----
#pragma unroll
    for (int i = 0; i < 4; i++) {
        int pa = p0 + wm * 64 + i * 16 + (lane >> 2);
        int pb = pa + 8;
#pragma unroll
        for (int j = 0; j < 8; j++) {
            int f = f0 + wn * 64 + j * 8 + (lane & 3) * 2;
            float2 bj = *(const float2*)(bias + f);
            float v0 = fmaxf(acc[i][j][0] + bj.x, 0.f);
            float v1 = fmaxf(acc[i][j][1] + bj.y, 0.f);
            float v2 = fmaxf(acc[i][j][2] + bj.x, 0.f);
            float v3 = fmaxf(acc[i][j][3] + bj.y, 0.f);
            if (CVTOUT) {
                if (pa < M) *(uint32_t*)(Ch + (size_t)pa * Nf + f) = packh2(v0, v1);
                if (pb < M) *(uint32_t*)(Ch + (size_t)pb * Nf + f) = packh2(v2, v3);
            } else {
                if (pa < M) *(float2*)(C + (size_t)pa * Nf + f) = make_float2(v0, v1);
                if (pb < M) *(float2*)(C + (size_t)pb * Nf + f) = make_float2(v2, v3);
            }
        }
    }
}

// ---------------------------------------------------------------------------
extern "C" void kernel_launch(void* const* d_in, const int* in_sizes, int n_in,
                              void* d_out, int out_size)
{
    const float* inp = (const float*)d_in[0];
    const int*   idx = (const int*)d_in[1];   // int32 (JAX x64 disabled)
    const float* W1  = (const float*)d_in[2];
    const float* b1  = (const float*)d_in[3];
    const float* W2  = (const float*)d_in[4];
    const float* b2  = (const float*)d_in[5];
    const float* Wv1 = (const float*)d_in[6];
    const float* bv1 = (const float*)d_in[7];
    const float* W3  = (const float*)d_in[8];
    const float* b3  = (const float*)d_in[9];
    const float* W4  = (const float*)d_in[10];
    const float* b4  = (const float*)d_in[11];
    const float* Wv2 = (const float*)d_in[12];
    const float* bv2 = (const float*)d_in[13];
    float* out = (float*)d_out;

    __half *pf1h, *pf2h, *pf4h, *pf5h, *vox1h, *vgh, *vox2h, *wth;
    cudaGetSymbolAddress((void**)&pf1h,  g_pf1h);
    cudaGetSymbolAddress((void**)&pf2h,  g_pf2h);
    cudaGetSymbolAddress((void**)&pf4h,  g_pf4h);
    cudaGetSymbolAddress((void**)&pf5h,  g_pf5h);
    cudaGetSymbolAddress((void**)&vox1h, g_vox1h);
    cudaGetSymbolAddress((void**)&vgh,   g_vgh);
    cudaGetSymbolAddress((void**)&vox2h, g_vox2h);
    cudaGetSymbolAddress((void**)&wth,   g_wth);

    const int SMEM = 3 * 20480 + 512;
    cudaFuncSetAttribute(k_hmma<2,0,1>, cudaFuncAttributeMaxDynamicSharedMemorySize, SMEM);
    cudaFuncSetAttribute(k_hmma<4,0,1>, cudaFuncAttributeMaxDynamicSharedMemorySize, SMEM);
    cudaFuncSetAttribute(k_hmma<8,1,1>, cudaFuncAttributeMaxDynamicSharedMemorySize, SMEM);
    cudaFuncSetAttribute(k_hmma<8,0,1>, cudaFuncAttributeMaxDynamicSharedMemorySize, SMEM);
    cudaFuncSetAttribute(k_hmma<8,0,0>, cudaFuncAttributeMaxDynamicSharedMemorySize, SMEM);

    // CSR build
    k_zcnt<<<(NVOX + 255) / 256, 256>>>();
    k_prep<<<(221184 + 255) / 256, 256>>>(Wv1, W3, W4, Wv2, W2);
    k_hist<<<(NPTS + 255) / 256, 256>>>(idx);
    k_scan1<<<64, 1024>>>();
    k_scan2<<<1, 64>>>();
    k_scan3<<<64, 1024>>>();
    k_scatter<<<(NPTS + 255) / 256, 256>>>(idx);

    // 1a) point MLP 6->64 -> pf1 fp16
    k1a_pointwise<<<(NPTS + 255) / 256, 256>>>(inp, W1, b1);
    // 1b) pf2 = relu(pf1 @ W2 + b2) -> fp16
    k_hmma<2,0,1><<<dim3((NPTS + 127) / 128, 1), 128, SMEM>>>(
        pf1h, nullptr, nullptr, wth + 212992, b2, nullptr, pf2h, NPTS, 128);
    // 1c) vox1 = segment-max(pf2) via CSR gather
    k_vmax<128><<<NVOX / 2, 128>>>(pf2h, vox1h);

    // 2) vg = relu(vox1 @ Wv1 + bv1) -> fp16
    k_hmma<4,0,1><<<dim3(NVOX / 128, 1), 128, SMEM>>>(
        vox1h, nullptr, nullptr, wth + 0, bv1, nullptr, vgh, NVOX, 128);
    // 3) pf4 = relu(concat(vg[idx], pf2) @ W3 + b3) -> fp16
    k_hmma<8,1,1><<<dim3((NPTS + 127) / 128, 2), 128, SMEM>>>(
        pf2h, vgh, idx, wth + 16384, b3, nullptr, pf4h, NPTS, 256);
    // 4) pf5 = relu(pf4 @ W4 + b4) -> fp16
    k_hmma<8,0,1><<<dim3((NPTS + 127) / 128, 2), 128, SMEM>>>(
        pf4h, nullptr, nullptr, wth + 81920, b4, nullptr, pf5h, NPTS, 256);
    // 4b) vox2 = segment-max(pf5) via CSR gather
    k_vmax<256><<<NVOX, 128>>>(pf5h, vox2h);

    // 5) out = relu(vox2 @ Wv2 + bv2) (fp32 store)
    k_hmma<8,0,0><<<dim3(NVOX / 128, 2), 128, SMEM>>>(
        vox2h, nullptr, nullptr, wth + 147456, bv2, out, nullptr, NVOX, 256);
}

// round 16
// speedup vs baseline: 1.0916x; 1.0326x over previous
#include <cuda_runtime.h>
#include <cuda_fp16.h>
#include <cstdint>

#define NPTS 500000
#define NVOX 65536

// fp16 activation buffers
static __device__ __align__(16) __half g_pf1h [(size_t)NPTS * 64];
static __device__ __align__(16) __half g_pf2h [(size_t)NPTS * 128];
static __device__ __align__(16) __half g_pf4h [(size_t)NPTS * 256];
static __device__ __align__(16) __half g_pf5h [(size_t)NPTS * 256];
static __device__ __align__(16) __half g_vox1h[(size_t)NVOX * 128];
static __device__ __align__(16) __half g_vgh  [(size_t)NVOX * 128];
static __device__ __align__(16) __half g_vox2h[(size_t)NVOX * 256];
// Pre-transposed fp16 weights: [Wv1t 128x128][W3t 256x256][W4t][Wv2t][W2t 128x64]
static __device__ __align__(16) __half g_wth[221184];
// CSR structures for segment-max
static __device__ int g_cnt [NVOX];
static __device__ int g_offs[NVOX + 1];
static __device__ int g_cur [NVOX];
static __device__ int g_plist[NPTS];
static __device__ int g_bsum[64];

__device__ __forceinline__ uint32_t smem_u32(const void* p) {
    return (uint32_t)__cvta_generic_to_shared((void*)p);
}
__device__ __forceinline__ uint32_t packh2(float a, float b) {
    __half2 p = __floats2half2_rn(a, b);
    return *reinterpret_cast<uint32_t*>(&p);
}
__device__ __forceinline__ void ldmx4(uint32_t* r, uint32_t addr) {
    asm volatile("ldmatrix.sync.aligned.m8n8.x4.shared.b16 {%0,%1,%2,%3}, [%4];"
                 : "=r"(r[0]), "=r"(r[1]), "=r"(r[2]), "=r"(r[3]) : "r"(addr));
}
__device__ __forceinline__ void mma16816(float* d, const uint32_t* a, uint32_t b0, uint32_t b1) {
    asm volatile(
        "mma.sync.aligned.m16n8k16.row.col.f32.f16.f16.f32 "
        "{%0,%1,%2,%3}, {%4,%5,%6,%7}, {%8,%9}, {%0,%1,%2,%3};"
        : "+f"(d[0]), "+f"(d[1]), "+f"(d[2]), "+f"(d[3])
        : "r"(a[0]), "r"(a[1]), "r"(a[2]), "r"(a[3]), "r"(b0), "r"(b1));
}
__device__ __forceinline__ void cp16(uint32_t dst, const void* src, bool pred) {
    int sz = pred ? 16 : 0;
    asm volatile("cp.async.cg.shared.global [%0], [%1], 16, %2;"
                 :: "r"(dst), "l"(src), "r"(sz));
}
__device__ __forceinline__ void cp_commit() { asm volatile("cp.async.commit_group;"); }
__device__ __forceinline__ void cp_wait0()  { asm volatile("cp.async.wait_group 0;" ::: "memory"); }
__device__ __forceinline__ void cp_wait1()  { asm volatile("cp.async.wait_group 1;" ::: "memory"); }

// ---------------------------------------------------------------------------
// CSR build: zero counts -> histogram -> 3-phase scan -> scatter
// ---------------------------------------------------------------------------
__global__ void k_zcnt() {
    int i = blockIdx.x * 256 + threadIdx.x;
    if (i < NVOX) g_cnt[i] = 0;
}
__global__ void k_hist(const int* __restrict__ idx) {
    int i = blockIdx.x * 256 + threadIdx.x;
    if (i < NPTS) atomicAdd(&g_cnt[idx[i]], 1);
}
__global__ __launch_bounds__(1024) void k_scan1() {
    __shared__ int ss[1024];
    int t = threadIdx.x, b = blockIdx.x;
    int i = b * 1024 + t;
    int c = g_cnt[i];
    ss[t] = c;
    __syncthreads();
    for (int d = 1; d < 1024; d <<= 1) {
        int v = (t >= d) ? ss[t - d] : 0;
        __syncthreads();
        ss[t] += v;
        __syncthreads();
    }
    g_offs[i] = ss[t] - c;
    if (t == 1023) g_bsum[b] = ss[1023];
}
__global__ void k_scan2() {
    int t = threadIdx.x;                   // 64 threads
    __shared__ int sb[64];
    sb[t] = g_bsum[t];
    __syncthreads();
    if (t == 0) {
        int run = 0;
        for (int j = 0; j < 64; j++) { int c = sb[j]; sb[j] = run; run += c; }
        g_offs[NVOX] = run;
    }
    __syncthreads();
    g_bsum[t] = sb[t];
}
__global__ __launch_bounds__(1024) void k_scan3() {
    int t = threadIdx.x, b = blockIdx.x;
    int i = b * 1024 + t;
    int o = g_offs[i] + g_bsum[b];
    g_offs[i] = o;
    g_cur [i] = o;
}
__global__ void k_scatter(const int* __restrict__ idx) {
    int i = blockIdx.x * 256 + threadIdx.x;
    if (i < NPTS) {
        int v = idx[i];
        int pos = atomicAdd(&g_cur[v], 1);
        g_plist[pos] = i;
    }
}

// ---------------------------------------------------------------------------
// Per-voxel gather-max over CSR list (fp16, __hmax2). Empty voxel -> 0.
// ---------------------------------------------------------------------------
template <int NF>
__global__ __launch_bounds__(128) void k_vmax(const __half* __restrict__ src,
                                              __half* __restrict__ dst) {
    int t = threadIdx.x;
    int v, h2;
    if (NF == 256) { v = blockIdx.x;             h2 = t; }
    else           { v = blockIdx.x * 2 + (t >> 6); h2 = t & 63; }
    int s = g_offs[v], e = g_offs[v + 1];
    __half2 acc = __float2half2_rn(0.f);
    const __half2* sp = (const __half2*)src;
    for (int q = s; q < e; q++) {
        int p = g_plist[q];
        acc = __hmax2(acc, sp[(size_t)p * (NF / 2) + h2]);
    }
    ((__half2*)dst)[(size_t)v * (NF / 2) + h2] = acc;
}

// ---------------------------------------------------------------------------
// Weight prep: W[K,Nf] fp32 -> Wt[Nf,K] fp16 (transposed)
// ---------------------------------------------------------------------------
__global__ void k_prep(const float* __restrict__ Wv1, const float* __restrict__ W3,
                       const float* __restrict__ W4,  const float* __restrict__ Wv2,
                       const float* __restrict__ W2) {
    int i = blockIdx.x * 256 + threadIdx.x;
    if (i >= 221184) return;
    const float* W; int K, Nf, j = i;
    if (i < 16384)       { W = Wv1; K = 128; Nf = 128; }
    else if (i < 81920)  { W = W3;  K = 256; Nf = 256; j = i - 16384; }
    else if (i < 147456) { W = W4;  K = 256; Nf = 256; j = i - 81920; }
    else if (i < 212992) { W = Wv2; K = 256; Nf = 256; j = i - 147456; }
    else                 { W = W2;  K = 64;  Nf = 128; j = i - 212992; }
    int n = j / K, k = j - n * K;
    g_wth[i] = __float2half_rn(W[(size_t)k * Nf + n]);
}

// ---------------------------------------------------------------------------
// K1a: per-point MLP 6 -> 64, write pf1 fp16
// ---------------------------------------------------------------------------
__global__ __launch_bounds__(256) void k1a_pointwise(
    const float* __restrict__ inp,
    const float* __restrict__ W1, const float* __restrict__ b1)
{
    __shared__ __align__(16) float sW1[6 * 64];
    __shared__ __align__(16) float sb1[64];
    int t = threadIdx.x;
    for (int i = t; i < 6 * 64; i += 256) sW1[i] = W1[i];
    if (t < 64) sb1[t] = b1[t];
    __syncthreads();

    int i = blockIdx.x * 256 + t;
    if (i >= NPTS) return;

    float x[6];
#pragma unroll
    for (int c = 0; c < 6; c++) x[c] = inp[(size_t)i * 6 + c];

    uint32_t outv[32];
#pragma unroll
    for (int j2 = 0; j2 < 32; j2++) {
        float a0 = sb1[j2 * 2], a1 = sb1[j2 * 2 + 1];
#pragma unroll
        for (int c = 0; c < 6; c++) {
            a0 = fmaf(x[c], sW1[c * 64 + j2 * 2], a0);
            a1 = fmaf(x[c], sW1[c * 64 + j2 * 2 + 1], a1);
        }
        outv[j2] = packh2(fmaxf(a0, 0.f), fmaxf(a1, 0.f));
    }
    uint4* dst = (uint4*)(g_pf1h + (size_t)i * 64);
#pragma unroll
    for (int q = 0; q < 8; q++) dst[q] = ((uint4*)outv)[q];
}

// ---------------------------------------------------------------------------
// HMMA GEMM, fp16: C[p,f] = relu( A[p,:] . Wt[f,:] + bias[f] )
// Block 128x128, K-chunk 32, 4 warps (64x64 warp tile), 3-stage cp.async,
// 128 threads. Inner loop software-pipelined: both k16-steps' ldmatrix loads
// issue before any MMA (LDS latency hidden under HMMA execution).
//   MODEB 0: A rows from ah[p*K + k]
//   MODEB 1: k<128 from gh[idx[p]*128+k], else ah[p*128 + (k-128)]
//   CVTOUT 1: fp16 store Ch;  CVTOUT 0: fp32 store C
// Stage layout: A[128x80B] @0, B @10240  (stage = 20480B)
// ---------------------------------------------------------------------------
template <int KCHUNKS, int MODEB, int CVTOUT>
__global__ __launch_bounds__(128) void k_hmma(
    const __half* __restrict__ ah, const __half* __restrict__ gh,
    const int* __restrict__ idx,
    const __half* __restrict__ wth,
    const float* __restrict__ bias,
    float* __restrict__ C, __half* __restrict__ Ch,
    int M, int Nf)
{
    constexpr int K = KCHUNKS * 32;
    constexpr int STG = 20480;
    constexpr int AOFF = 0, BOFF = 10240;
    constexpr int IDX_OFF = 3 * STG;

    extern __shared__ char sm[];
    int* sIdx = (int*)(sm + IDX_OFF);
    uint32_t smb = smem_u32(sm);

    int t = threadIdx.x;
    int lane = t & 31;
    int w = t >> 5;
    int wm = w & 1, wn = w >> 1;
    int p0 = blockIdx.x * 128;
    int f0 = blockIdx.y * 128;

    if (MODEB == 1) {
        if (t < 128) sIdx[t] = (p0 + t < M) ? idx[p0 + t] : 0;
        __syncthreads();
    }

    auto fill = [&](int s, int c) {
        int k0 = c * 32;
        uint32_t base = smb + s * STG;
#pragma unroll
        for (int it = 0; it < 4; it++) {
            int e = t + it * 128;
            int row = e >> 2, q = e & 3;
            int gp = p0 + row;
            const __half* srcp;
            if (MODEB == 0) {
                srcp = ah + (size_t)gp * K + k0 + q * 8;
            } else {
                if (k0 < 128) srcp = gh + (size_t)sIdx[row] * 128 + k0 + q * 8;
                else          srcp = ah + (size_t)gp * 128 + (k0 - 128) + q * 8;
            }
            cp16(base + AOFF + row * 80 + q * 16, srcp, gp < M);
        }
#pragma unroll
        for (int it = 0; it < 4; it++) {
            int e = t + it * 128;
            int n = e >> 2, q = e & 3;
            const __half* srcp = wth + (size_t)(f0 + n) * K + k0 + q * 8;
            cp16(base + BOFF + n * 80 + q * 16, srcp, true);
        }
        cp_commit();
    };

    float acc[4][8][4];
#pragma unroll
    for (int i = 0; i < 4; i++)
#pragma unroll
        for (int j = 0; j < 8; j++)
#pragma unroll
            for (int r = 0; r < 4; r++) acc[i][j][r] = 0.f;

    int ar  = ((lane >> 3) & 1) * 8 + (lane & 7);
    int akb = (lane >> 4) * 16;
    int bn  = (lane >> 4) * 8 + (lane & 7);
    int bkb = ((lane >> 3) & 1) * 16;

    fill(0, 0);
    if (KCHUNKS > 1) fill(1, 1);

#pragma unroll 1
    for (int c = 0; c < KCHUNKS; c++) {
        if (c + 1 < KCHUNKS) cp_wait1(); else cp_wait0();
        __syncthreads();
        if (c + 2 < KCHUNKS) fill((c + 2) % 3, c + 2);
        uint32_t base = smb + (c % 3) * STG;

        // ---- software-pipelined inner loop: ALL loads first, then MMAs ----
        uint32_t a[2][4][4], bh[2][4][4];
#pragma unroll
        for (int ks = 0; ks < 2; ks++) {
            int kb = ks * 32;
#pragma unroll
            for (int i = 0; i < 4; i++)
                ldmx4(a[ks][i], base + AOFF + (uint32_t)(wm * 64 + i * 16 + ar) * 80 + kb + akb);
#pragma unroll
            for (int j2 = 0; j2 < 4; j2++)
                ldmx4(bh[ks][j2], base + BOFF + (uint32_t)(wn * 64 + j2 * 16 + bn) * 80 + kb + bkb);
        }
#pragma unroll
        for (int ks = 0; ks < 2; ks++)
#pragma unroll
            for (int i = 0; i < 4; i++)
#pragma unroll
                for (int j = 0; j < 8; j++)
                    mma16816(acc[i][j], a[ks][i],
                             bh[ks][j >> 1][(j & 1) * 2], bh[ks][j >> 1][(j & 1) * 2 + 1]);
        // NOTE: no bottom __syncthreads — the top-of-loop barrier at iter c+1
        // orders these smem reads before any fill targeting this stage.
    }

    // ---- epilogue: bias + relu, store ----
#pragma unroll
    for (int i = 0; i < 4; i++) {
        int pa = p0 + wm * 64 + i * 16 + (lane >> 2);
        int pb = pa + 8;
#pragma unroll
        for (int j = 0; j < 8; j++) {
            int f = f0 + wn * 64 + j * 8 + (lane & 3) * 2;
            float2 bj = *(const float2*)(bias + f);
            float v0 = fmaxf(acc[i][j][0] + bj.x, 0.f);
            float v1 = fmaxf(acc[i][j][1] + bj.y, 0.f);
            float v2 = fmaxf(acc[i][j][2] + bj.x, 0.f);
            float v3 = fmaxf(acc[i][j][3] + bj.y, 0.f);
            if (CVTOUT) {
                if (pa < M) *(uint32_t*)(Ch + (size_t)pa * Nf + f) = packh2(v0, v1);
                if (pb < M) *(uint32_t*)(Ch + (size_t)pb * Nf + f) = packh2(v2, v3);
            } else {
                if (pa < M) *(float2*)(C + (size_t)pa * Nf + f) = make_float2(v0, v1);
                if (pb < M) *(float2*)(C + (size_t)pb * Nf + f) = make_float2(v2, v3);
            }
        }
    }
}

// ---------------------------------------------------------------------------
extern "C" void kernel_launch(void* const* d_in, const int* in_sizes, int n_in,
                              void* d_out, int out_size)
{
    const float* inp = (const float*)d_in[0];
    const int*   idx = (const int*)d_in[1];   // int32 (JAX x64 disabled)
    const float* W1  = (const float*)d_in[2];
    const float* b1  = (const float*)d_in[3];
    const float* W2  = (const float*)d_in[4];
    const float* b2  = (const float*)d_in[5];
    const float* Wv1 = (const float*)d_in[6];
    const float* bv1 = (const float*)d_in[7];
    const float* W3  = (const float*)d_in[8];
    const float* b3  = (const float*)d_in[9];
    const float* W4  = (const float*)d_in[10];
    const float* b4  = (const float*)d_in[11];
    const float* Wv2 = (const float*)d_in[12];
    const float* bv2 = (const float*)d_in[13];
    float* out = (float*)d_out;

    __half *pf1h, *pf2h, *pf4h, *pf5h, *vox1h, *vgh, *vox2h, *wth;
    cudaGetSymbolAddress((void**)&pf1h,  g_pf1h);
    cudaGetSymbolAddress((void**)&pf2h,  g_pf2h);
    cudaGetSymbolAddress((void**)&pf4h,  g_pf4h);
    cudaGetSymbolAddress((void**)&pf5h,  g_pf5h);
    cudaGetSymbolAddress((void**)&vox1h, g_vox1h);
    cudaGetSymbolAddress((void**)&vgh,   g_vgh);
    cudaGetSymbolAddress((void**)&vox2h, g_vox2h);
    cudaGetSymbolAddress((void**)&wth,   g_wth);

    const int SMEM = 3 * 20480 + 512;
    cudaFuncSetAttribute(k_hmma<2,0,1>, cudaFuncAttributeMaxDynamicSharedMemorySize, SMEM);
    cudaFuncSetAttribute(k_hmma<4,0,1>, cudaFuncAttributeMaxDynamicSharedMemorySize, SMEM);
    cudaFuncSetAttribute(k_hmma<8,1,1>, cudaFuncAttributeMaxDynamicSharedMemorySize, SMEM);
    cudaFuncSetAttribute(k_hmma<8,0,1>, cudaFuncAttributeMaxDynamicSharedMemorySize, SMEM);
    cudaFuncSetAttribute(k_hmma<8,0,0>, cudaFuncAttributeMaxDynamicSharedMemorySize, SMEM);

    // CSR build
    k_zcnt<<<(NVOX + 255) / 256, 256>>>();
    k_prep<<<(221184 + 255) / 256, 256>>>(Wv1, W3, W4, Wv2, W2);
    k_hist<<<(NPTS + 255) / 256, 256>>>(idx);
    k_scan1<<<64, 1024>>>();
    k_scan2<<<1, 64>>>();
    k_scan3<<<64, 1024>>>();
    k_scatter<<<(NPTS + 255) / 256, 256>>>(idx);

    // 1a) point MLP 6->64 -> pf1 fp16
    k1a_pointwise<<<(NPTS + 255) / 256, 256>>>(inp, W1, b1);
    // 1b) pf2 = relu(pf1 @ W2 + b2) -> fp16
    k_hmma<2,0,1><<<dim3((NPTS + 127) / 128, 1), 128, SMEM>>>(
        pf1h, nullptr, nullptr, wth + 212992, b2, nullptr, pf2h, NPTS, 128);
    // 1c) vox1 = segment-max(pf2) via CSR gather
    k_vmax<128><<<NVOX / 2, 128>>>(pf2h, vox1h);

    // 2) vg = relu(vox1 @ Wv1 + bv1) -> fp16
    k_hmma<4,0,1><<<dim3(NVOX / 128, 1), 128, SMEM>>>(
        vox1h, nullptr, nullptr, wth + 0, bv1, nullptr, vgh, NVOX, 128);
    // 3) pf4 = relu(concat(vg[idx], pf2) @ W3 + b3) -> fp16
    k_hmma<8,1,1><<<dim3((NPTS + 127) / 128, 2), 128, SMEM>>>(
        pf2h, vgh, idx, wth + 16384, b3, nullptr, pf4h, NPTS, 256);
    // 4) pf5 = relu(pf4 @ W4 + b4) -> fp16
    k_hmma<8,0,1><<<dim3((NPTS + 127) / 128, 2), 128, SMEM>>>(
        pf4h, nullptr, nullptr, wth + 81920, b4, nullptr, pf5h, NPTS, 256);
    // 4b) vox2 = segment-max(pf5) via CSR gather
    k_vmax<256><<<NVOX, 128>>>(pf5h, vox2h);

    // 5) out = relu(vox2 @ Wv2 + bv2) (fp32 store)
    k_hmma<8,0,0><<<dim3(NVOX / 128, 2), 128, SMEM>>>(
        vox2h, nullptr, nullptr, wth + 147456, bv2, out, nullptr, NVOX, 256);
}